// round 12
// baseline (speedup 1.0000x reference)
#include <cuda_runtime.h>
#include <math.h>

#define FDIM 64
#define NMAX 100000
#define EMAX 1600000
#define BGR  64
#define PF 4            // cp.async ring stages (2 groups of 2 edges)

typedef unsigned long long ull;

// ---------------- f32x2 helpers ----------------
__device__ __forceinline__ void fma2(ull& acc, ull a, ull b) {
    asm("fma.rn.f32x2 %0, %1, %2, %0;" : "+l"(acc) : "l"(a), "l"(b));
}
__device__ __forceinline__ void add2(ull& acc, ull a) {
    asm("add.rn.f32x2 %0, %1, %0;" : "+l"(acc) : "l"(a));
}
__device__ __forceinline__ ull pack2(float lo, float hi) {
    ull o;
    asm("mov.b64 %0, {%1, %2};" : "=l"(o) : "r"(__float_as_uint(lo)), "r"(__float_as_uint(hi)));
    return o;
}
__device__ __forceinline__ void unpack2(ull v, float& lo, float& hi) {
    unsigned a, b;
    asm("mov.b64 {%0, %1}, %2;" : "=r"(a), "=r"(b) : "l"(v));
    lo = __uint_as_float(a); hi = __uint_as_float(b);
}
__device__ __forceinline__ void cp_async16(void* smem, const void* gmem) {
    unsigned s = (unsigned)__cvta_generic_to_shared(smem);
    asm volatile("cp.async.cg.shared.global [%0], [%1], 16;" :: "r"(s), "l"(gmem));
}
__device__ __forceinline__ void cp_commit() {
    asm volatile("cp.async.commit_group;");
}
__device__ __forceinline__ void cp_wait1() {
    asm volatile("cp.async.wait_group 1;");
}

// ---------------- device scratch ----------------
__device__ __align__(16) float g_C  [NMAX * FDIM];
__device__ __align__(16) float g_ys [NMAX * FDIM];
__device__ __align__(16) float g_zx [NMAX * FDIM];
__device__ __align__(16) float g_agg[(size_t)NMAX * 256];
__device__ float g_amp [NMAX];
__device__ float g_iamp[NMAX];
__device__ __align__(16) float g_out[NMAX * FDIM];
__device__ int   g_cnt [NMAX];
__device__ int   g_offs[NMAX];
__device__ int   g_fill[NMAX];
__device__ int2  g_csr [EMAX];     // (src, edge_id)
__device__ int   g_cursor;
__device__ __align__(16) float g_WoWl[832 * FDIM];
__device__ __align__(16) ull   g_W2[3 * 128 * FDIM];   // k-pair packed weights
__device__ __align__(16) float g_Md[32 * FDIM], g_Ms[32 * FDIM], g_Mx[32 * FDIM];
__device__ __align__(16) float g_Wec[16 * FDIM];
__device__ float g_Cc[FDIM], g_csv[FDIM], g_cxv[FDIM];
__device__ float g_bnS[FDIM], g_bnQ[FDIM], g_bnA[FDIM], g_bnB[FDIM];
__device__ float g_pool[BGR * FDIM];

// ---------------- init ----------------
__global__ void k_init(int Nn) {
    int i = blockIdx.x * blockDim.x + threadIdx.x;
    if (i < Nn) g_cnt[i] = 0;
    if (i < BGR * FDIM) g_pool[i] = 0.f;
    if (i < FDIM) { g_bnS[i] = 0.f; g_bnQ[i] = 0.f; }
    if (i == 0) g_cursor = 0;
}

// ---------------- WoWl = Wo @ Wl  (832x64) ----------------
__global__ void k_wowl(const float* __restrict__ Wo, const float* __restrict__ Wl) {
    int idx = blockIdx.x * blockDim.x + threadIdx.x;
    if (idx >= 832 * FDIM) return;
    int r = idx >> 6, c = idx & 63;
    float a = 0.f;
    #pragma unroll
    for (int k = 0; k < FDIM; k++) a += Wo[r * FDIM + k] * Wl[k * FDIM + c];
    g_WoWl[idx] = a;
}

// ---------------- k-pair packed weight prep: g_W2[m][kp][c] ----------------
__global__ void k_wprep() {
    int idx = blockIdx.x * blockDim.x + threadIdx.x;
    if (idx >= 3 * 128 * FDIM) return;
    int c = idx & 63;
    int kp = (idx >> 6) & 127;
    int m = idx >> 13;
    int row = 64 + m * 256 + 2 * kp;
    g_W2[idx] = pack2(g_WoWl[row * 64 + c], g_WoWl[(row + 1) * 64 + c]);
}

// ---------------- small folded-weight precompute (warp per output) ----------------
__global__ void k_small(const float* __restrict__ W2, const float* __restrict__ b2,
                        const float* __restrict__ Wp, const float* __restrict__ bp,
                        const float* __restrict__ We, const float* __restrict__ be,
                        const float* __restrict__ bo, const float* __restrict__ Wl,
                        const float* __restrict__ bl) {
    int gw = (blockIdx.x * blockDim.x + threadIdx.x) >> 5;
    int lane = threadIdx.x & 31;
    if (gw >= 7360) return;
    int k0 = lane, k1 = lane + 32;
    float a = 0.f;
    if (gw < 2048) {
        int i = gw >> 6, c = gw & 63;
        a = W2[i*64+k0]*Wp[k0*64+c] + W2[i*64+k1]*Wp[k1*64+c];
    } else if (gw < 4096) {
        int t = gw - 2048; int i = t >> 6, c = t & 63;
        a = W2[i*64+k0]*Wp[(64+k0)*64+c] + W2[i*64+k1]*Wp[(64+k1)*64+c];
    } else if (gw < 6144) {
        int t = gw - 4096; int i = t >> 6, c = t & 63;
        a = W2[i*64+k0]*g_WoWl[k0*64+c] + W2[i*64+k1]*g_WoWl[k1*64+c];
    } else if (gw < 7168) {
        int t = gw - 6144; int i = t >> 6, c = t & 63;
        a = We[i*64+k0]*Wp[(128+k0)*64+c] + We[i*64+k1]*Wp[(128+k1)*64+c];
    } else if (gw < 7232) {
        int c = gw - 7168;
        a = be[k0]*Wp[(128+k0)*64+c] + b2[k0]*Wp[k0*64+c]
          + be[k1]*Wp[(128+k1)*64+c] + b2[k1]*Wp[k1*64+c];
    } else if (gw < 7296) {
        int c = gw - 7232;
        a = b2[k0]*Wp[(64+k0)*64+c] + b2[k1]*Wp[(64+k1)*64+c];
    } else {
        int c = gw - 7296;
        a = bo[k0]*Wl[k0*64+c] + b2[k0]*g_WoWl[k0*64+c]
          + bo[k1]*Wl[k1*64+c] + b2[k1]*g_WoWl[k1*64+c];
    }
    #pragma unroll
    for (int o = 16; o; o >>= 1) a += __shfl_xor_sync(0xffffffffu, a, o);
    if (lane == 0) {
        if (gw < 2048) g_Md[gw] = a;
        else if (gw < 4096) g_Ms[gw - 2048] = a;
        else if (gw < 6144) g_Mx[gw - 4096] = a;
        else if (gw < 7168) g_Wec[gw - 6144] = a;
        else if (gw < 7232) g_Cc[gw - 7168] = a + bp[gw - 7168];
        else if (gw < 7296) g_csv[gw - 7232] = a;
        else g_cxv[gw - 7296] = a + bl[gw - 7296];
    }
}

// ---------------- node pre-pass (scalar, 79 regs) ----------------
__global__ __launch_bounds__(256) void k_node(const float* __restrict__ x,
                                              const float* __restrict__ W1,
                                              const float* __restrict__ b1, int Nn) {
    __shared__ float sW1[64 * 32];
    __shared__ float sM[3][32 * 64];
    __shared__ float sb1[32];
    __shared__ float sC[3][64];
    int tid = threadIdx.x;
    for (int i = tid; i < 64 * 32; i += 256) sW1[i] = W1[i];
    for (int i = tid; i < 32 * 64; i += 256) {
        sM[0][i] = g_Md[i]; sM[1][i] = g_Ms[i]; sM[2][i] = g_Mx[i];
    }
    if (tid < 32) sb1[tid] = b1[tid];
    if (tid < 64) { sC[0][tid] = g_Cc[tid]; sC[1][tid] = g_csv[tid]; sC[2][tid] = g_cxv[tid]; }
    __syncthreads();
    int n = blockIdx.x * 256 + tid;
    if (n >= Nn) return;

    float xr[64];
    const float4* xp = (const float4*)(x + (size_t)n * 64);
    #pragma unroll
    for (int i = 0; i < 16; i++) {
        float4 v = xp[i];
        xr[4*i] = v.x; xr[4*i+1] = v.y; xr[4*i+2] = v.z; xr[4*i+3] = v.w;
    }
    float t[32];
    #pragma unroll
    for (int j = 0; j < 32; j += 4) {
        float a0 = sb1[j], a1 = sb1[j+1], a2 = sb1[j+2], a3 = sb1[j+3];
        #pragma unroll
        for (int i = 0; i < 64; i++) {
            float xi = xr[i];
            const float* w = &sW1[i * 32 + j];
            a0 += xi * w[0]; a1 += xi * w[1]; a2 += xi * w[2]; a3 += xi * w[3];
        }
        t[j] = fmaxf(a0, 0.f); t[j+1] = fmaxf(a1, 0.f);
        t[j+2] = fmaxf(a2, 0.f); t[j+3] = fmaxf(a3, 0.f);
    }
    float* out0 = g_C  + (size_t)n * 64;
    float* out1 = g_ys + (size_t)n * 64;
    float* out2 = g_zx + (size_t)n * 64;
    #pragma unroll
    for (int m = 0; m < 3; m++) {
        float* op = (m == 0) ? out0 : (m == 1) ? out1 : out2;
        #pragma unroll
        for (int j = 0; j < 64; j += 4) {
            float a0 = sC[m][j], a1 = sC[m][j+1], a2 = sC[m][j+2], a3 = sC[m][j+3];
            #pragma unroll
            for (int i = 0; i < 32; i++) {
                float ti = t[i];
                const float* w = &sM[m][i * 64 + j];
                a0 += ti * w[0]; a1 += ti * w[1]; a2 += ti * w[2]; a3 += ti * w[3];
            }
            float4 v; v.x = a0; v.y = a1; v.z = a2; v.w = a3;
            *(float4*)(op + j) = v;
        }
    }
}

// ---------------- CSR build ----------------
__global__ void k_count(const int* __restrict__ ei, int En) {
    int e = blockIdx.x * blockDim.x + threadIdx.x;
    if (e >= En) return;
    atomicAdd(&g_cnt[ei[En + e]], 1);
}

__global__ void k_scan(int Nn) {
    __shared__ int s[1024];
    __shared__ int base;
    int tid = threadIdx.x;
    int n = blockIdx.x * 1024 + tid;
    int c = (n < Nn) ? g_cnt[n] : 0;
    s[tid] = c;
    __syncthreads();
    for (int d = 1; d < 1024; d <<= 1) {
        int v = (tid >= d) ? s[tid - d] : 0;
        __syncthreads();
        s[tid] += v;
        __syncthreads();
    }
    if (tid == 1023) base = atomicAdd(&g_cursor, s[1023]);
    __syncthreads();
    if (n < Nn) {
        int off = base + s[tid] - c;
        g_offs[n] = off;
        g_fill[n] = off;
    }
}

__global__ void k_fill(const int* __restrict__ ei, int En) {
    int e = blockIdx.x * blockDim.x + threadIdx.x;
    if (e >= En) return;
    int d = ei[En + e];
    int s = ei[e];
    int p = atomicAdd(&g_fill[d], 1);
    g_csr[p] = make_int2(s, e);
}

// ---------------- agg edge body (packed k-pairs) ----------------
__device__ __forceinline__ void agg_body(ulonglong2 u0, ulonglong2 u1,
                                         ulonglong2 u2, ulonglong2 u3,
                                         float cya, float cyb,
                                         const ull* wq0, const ull* wq1,
                                         ull& s2, ull& q2,
                                         float& mn0, float& mx0, float& mn1, float& mx1) {
    ull mA = 0ull, mB = 0ull;
    fma2(mA, u0.x, wq0[0]); fma2(mB, u0.x, wq1[0]);
    fma2(mA, u0.y, wq0[1]); fma2(mB, u0.y, wq1[1]);
    fma2(mA, u1.x, wq0[2]); fma2(mB, u1.x, wq1[2]);
    fma2(mA, u1.y, wq0[3]); fma2(mB, u1.y, wq1[3]);
    fma2(mA, u2.x, wq0[4]); fma2(mB, u2.x, wq1[4]);
    fma2(mA, u2.y, wq0[5]); fma2(mB, u2.y, wq1[5]);
    fma2(mA, u3.x, wq0[6]); fma2(mB, u3.x, wq1[6]);
    fma2(mA, u3.y, wq0[7]); fma2(mB, u3.y, wq1[7]);
    float alo, ahi, blo, bhi;
    unpack2(mA, alo, ahi); unpack2(mB, blo, bhi);
    float m0 = (alo + ahi) + cya;
    float m1 = (blo + bhi) + cyb;
    ull m01 = pack2(m0, m1);
    add2(s2, m01);
    fma2(q2, m01, m01);
    mn0 = fminf(mn0, m0); mx0 = fmaxf(mx0, m0);
    mn1 = fminf(mn1, m1); mx1 = fmaxf(mx1, m1);
}

__device__ __forceinline__ void agg_finish(int n, int d0, ull s2, ull q2,
                                           float mn0, float mx0, float mn1, float mx1,
                                           int lane, float avg_log) {
    float s0, s1, q0, q1;
    unpack2(s2, s0, s1); unpack2(q2, q0, q1);
    float d = (float)((d0 > 1) ? d0 : 1);
    float inv_d = 1.f / d;
    float C0 = g_C[(size_t)n * 64 + lane], C1 = g_C[(size_t)n * 64 + 32 + lane];
    float mu0 = s0 * inv_d, mu1 = s1 * inv_d;
    float sd0 = sqrtf(fmaxf(q0 * inv_d - mu0 * mu0, 0.f) + 1e-5f);
    float sd1 = sqrtf(fmaxf(q1 * inv_d - mu1 * mu1, 0.f) + 1e-5f);
    float mean0, mean1;
    if (d0 > 0) {
        mean0 = mu0 + C0; mn0 += C0; mx0 += C0;
        mean1 = mu1 + C1; mn1 += C1; mx1 += C1;
    } else {
        mean0 = 0.f; mn0 = 0.f; mx0 = 0.f;
        mean1 = 0.f; mn1 = 0.f; mx1 = 0.f;
    }
    float amp = logf(d + 1.f) / avg_log;
    float iamp = 1.f / amp;
    float* A = g_agg + (size_t)n * 256;
    A[lane]       = mean0; A[32 + lane]  = mean1;
    A[64 + lane]  = mn0;   A[96 + lane]  = mn1;
    A[128 + lane] = mx0;   A[160 + lane] = mx1;
    A[192 + lane] = sd0;   A[224 + lane] = sd1;
    if (lane == 0) { g_amp[n] = amp; g_iamp[n] = iamp; }
}

// ---------------- aggregation: warp per node, 2-edge groups, cp.async ring ------
__global__ __launch_bounds__(256) void k_agg(const float* __restrict__ ea, int Nn, float avg_log) {
    __shared__ __align__(16) float sEA[8][PF][16];
    int lane = threadIdx.x & 31;
    int w = threadIdx.x >> 5;
    int n = (blockIdx.x * 256 + threadIdx.x) >> 5;
    if (n >= Nn) return;

    ull wq0[8], wq1[8];
    #pragma unroll
    for (int kp = 0; kp < 8; kp++) {
        wq0[kp] = pack2(g_Wec[(2*kp)*64 + lane],      g_Wec[(2*kp+1)*64 + lane]);
        wq1[kp] = pack2(g_Wec[(2*kp)*64 + 32 + lane], g_Wec[(2*kp+1)*64 + 32 + lane]);
    }
    int off = g_offs[n];
    int d0 = g_cnt[n];
    ull s2 = 0ull, q2 = 0ull;
    float mn0 = 3.4e38f, mn1 = 3.4e38f, mx0 = -3.4e38f, mx1 = -3.4e38f;

    // prologue: 2 groups of 2 edges (stages 0..3). lanes 0-7: lane>>2 = edge-in-group.
    #pragma unroll
    for (int g = 0; g < 2; g++) {
        int j = 2 * g + (lane >> 2);
        if (lane < 8 && j < d0) {
            int eid = g_csr[off + j].y;
            cp_async16(&sEA[w][j][(lane & 3) * 4], ea + (size_t)eid * 16 + (lane & 3) * 4);
        }
        cp_commit();
    }

    if (d0 > 0) {
        // ys for edges 0,1
        int2 e0 = g_csr[off];
        int2 e1 = g_csr[off + ((d0 > 1) ? 1 : 0)];
        float cy0a = g_ys[(size_t)e0.x * 64 + lane], cy0b = g_ys[(size_t)e0.x * 64 + 32 + lane];
        float cy1a = g_ys[(size_t)e1.x * 64 + lane], cy1b = g_ys[(size_t)e1.x * 64 + 32 + lane];

        for (int i = 0; i < d0; i += 2) {
            // prefetch ys for edges i+2, i+3 (clamped)
            float py0a = cy0a, py0b = cy0b, py1a = cy1a, py1b = cy1b;
            if (i + 2 < d0) {
                int i3 = (i + 3 < d0) ? (i + 3) : (d0 - 1);
                int2 e2 = g_csr[off + i + 2];
                int2 e3 = g_csr[off + i3];
                py0a = g_ys[(size_t)e2.x * 64 + lane]; py0b = g_ys[(size_t)e2.x * 64 + 32 + lane];
                py1a = g_ys[(size_t)e3.x * 64 + lane]; py1b = g_ys[(size_t)e3.x * 64 + 32 + lane];
            }
            cp_wait1();
            __syncwarp();
            const ulonglong2* p0 = (const ulonglong2*)sEA[w][i & 3];
            const ulonglong2* p1 = (const ulonglong2*)sEA[w][(i + 1) & 3];
            ulonglong2 a0 = p0[0], a1 = p0[1], a2 = p0[2], a3 = p0[3];
            ulonglong2 b0 = p1[0], b1 = p1[1], b2 = p1[2], b3 = p1[3];
            __syncwarp();
            // refill stages (i&3),(i+1&3) with edges i+4, i+5 as ONE group
            int j = i + 4 + (lane >> 2);
            if (lane < 8 && j < d0) {
                int eid = g_csr[off + j].y;
                cp_async16(&sEA[w][j & 3][(lane & 3) * 4], ea + (size_t)eid * 16 + (lane & 3) * 4);
            }
            cp_commit();
            agg_body(a0, a1, a2, a3, cy0a, cy0b, wq0, wq1, s2, q2, mn0, mx0, mn1, mx1);
            if (i + 1 < d0)
                agg_body(b0, b1, b2, b3, cy1a, cy1b, wq0, wq1, s2, q2, mn0, mx0, mn1, mx1);
            cy0a = py0a; cy0b = py0b; cy1a = py1a; cy1b = py1b;
        }
    }
    agg_finish(n, d0, s2, q2, mn0, mx0, mn1, mx1, lane, avg_log);
}

// ---------------- big GEMM: 256 thr, 64x64 tile, k-pair packed (no splats) ------
#define GBM 64
#define GBK 32
__global__ __launch_bounds__(256) void k_gemm(int Nn) {
    __shared__ __align__(16) float sA[GBM * GBK];
    __shared__ __align__(16) ull sW2[3 * 16 * 64];     // [m][kp][c]
    __shared__ float sS[64], sQ[64];
    int tid = threadIdx.x;
    if (tid < 64) { sS[tid] = 0.f; sQ[tid] = 0.f; }
    int bm = blockIdx.x * GBM;
    int r4 = (tid >> 4) << 2;       // rows r4..r4+3
    int c4 = (tid & 15) << 2;       // cols c4..c4+3

    ull acc2[3][4][4];
    #pragma unroll
    for (int m = 0; m < 3; m++)
        #pragma unroll
        for (int i = 0; i < 4; i++)
            #pragma unroll
            for (int c = 0; c < 4; c++) acc2[m][i][c] = 0ull;

    for (int k0 = 0; k0 < 256; k0 += GBK) {
        // A tile: 64x32 floats = 512 float4 / 256 thr = 2 each
        #pragma unroll
        for (int l = 0; l < 2; l++) {
            int lin = tid + 256 * l;
            int r = lin >> 3, kq = (lin & 7) << 2;
            int row = bm + r;
            float4 vz = make_float4(0.f, 0.f, 0.f, 0.f);
            float4 vv = (row < Nn) ? *(const float4*)(g_agg + (size_t)row * 256 + k0 + kq) : vz;
            *(float4*)&sA[r * GBK + kq] = vv;
        }
        // W2 tile: 3 x 16kp x 64 ull = 1536 ulonglong2 / 256 thr = 6 each
        #pragma unroll
        for (int l = 0; l < 6; l++) {
            int lin = tid + 256 * l;
            int m = lin >> 9, t2 = lin & 511;
            *(ulonglong2*)&sW2[m * 1024 + 2 * t2] =
                *(const ulonglong2*)&g_W2[m * 8192 + k0 * 32 + 2 * t2];
        }
        __syncthreads();
        #pragma unroll
        for (int kp = 0; kp < 16; kp++) {
            ull a2[4];
            #pragma unroll
            for (int i = 0; i < 4; i++)
                a2[i] = *(const ull*)&sA[(r4 + i) * GBK + 2 * kp];
            #pragma unroll
            for (int m = 0; m < 3; m++) {
                const ull* wrow = &sW2[m * 1024 + kp * 64 + c4];
                ulonglong2 wv0 = *(const ulonglong2*)&wrow[0];
                ulonglong2 wv1 = *(const ulonglong2*)&wrow[2];
                #pragma unroll
                for (int i = 0; i < 4; i++) {
                    fma2(acc2[m][i][0], a2[i], wv0.x);
                    fma2(acc2[m][i][1], a2[i], wv0.y);
                    fma2(acc2[m][i][2], a2[i], wv1.x);
                    fma2(acc2[m][i][3], a2[i], wv1.y);
                }
            }
        }
        __syncthreads();
    }

    // epilogue: horizontal sum, combine scalers, add zx, BN partials
    float lS[4] = {0.f, 0.f, 0.f, 0.f};
    float lQ[4] = {0.f, 0.f, 0.f, 0.f};
    #pragma unroll
    for (int i = 0; i < 4; i++) {
        int row = bm + r4 + i;
        if (row < Nn) {
            float amp = g_amp[row], ia = g_iamp[row];
            float4 z = *(const float4*)(g_zx + (size_t)row * 64 + c4);
            float zz[4] = {z.x, z.y, z.z, z.w};
            float o[4];
            #pragma unroll
            for (int c = 0; c < 4; c++) {
                float alo, ahi, blo, bhi, clo, chi;
                unpack2(acc2[0][i][c], alo, ahi);
                unpack2(acc2[1][i][c], blo, bhi);
                unpack2(acc2[2][i][c], clo, chi);
                o[c] = (alo + ahi) + amp * (blo + bhi) + ia * (clo + chi) + zz[c];
            }
            float4 ov; ov.x = o[0]; ov.y = o[1]; ov.z = o[2]; ov.w = o[3];
            *(float4*)(g_out + (size_t)row * 64 + c4) = ov;
            #pragma unroll
            for (int c = 0; c < 4; c++) { lS[c] += o[c]; lQ[c] += o[c] * o[c]; }
        }
    }
    #pragma unroll
    for (int c = 0; c < 4; c++) {
        atomicAdd(&sS[c4 + c], lS[c]);
        atomicAdd(&sQ[c4 + c], lQ[c]);
    }
    __syncthreads();
    if (tid < 64) {
        atomicAdd(&g_bnS[tid], sS[tid]);
        atomicAdd(&g_bnQ[tid], sQ[tid]);
    }
}

// ---------------- BN finalize ----------------
__global__ void k_bn(const float* __restrict__ gamma, const float* __restrict__ beta, int Nn) {
    int f = threadIdx.x;
    if (f >= 64) return;
    float inv_n = 1.f / (float)Nn;
    float mu = g_bnS[f] * inv_n;
    float var = g_bnQ[f] * inv_n - mu * mu;
    float sc = gamma[f] * rsqrtf(var + 1e-5f);
    g_bnA[f] = sc;
    g_bnB[f] = beta[f] - mu * sc;
}

// ---------------- pooling ----------------
__global__ void k_pool(const int* __restrict__ batch, int Nn) {
    int f = threadIdx.x & 63;
    int g = threadIdx.x >> 6;
    int n0 = blockIdx.x * 1024;
    float sc = g_bnA[f], sh = g_bnB[f];
    float acc = 0.f;
    int cur = -1;
    for (int i = g; i < 1024; i += 4) {
        int n = n0 + i;
        if (n >= Nn) break;
        int b = batch[n];
        float v = fmaxf(g_out[(size_t)n * 64 + f] * sc + sh, 0.f);
        if (b != cur) {
            if (cur >= 0) atomicAdd(&g_pool[cur * 64 + f], acc);
            cur = b; acc = v;
        } else {
            acc += v;
        }
    }
    if (cur >= 0) atomicAdd(&g_pool[cur * 64 + f], acc);
}

// ---------------- head MLP ----------------
__global__ void k_head(const float* __restrict__ Wm1, const float* __restrict__ bm1,
                       const float* __restrict__ Wm2, const float* __restrict__ bm2,
                       float* __restrict__ outp) {
    __shared__ float sp[64];
    __shared__ float red[128];
    int b = blockIdx.x, j = threadIdx.x;
    if (j < 64) sp[j] = g_pool[b * 64 + j];
    __syncthreads();
    float v = 0.f;
    if (j < 100) {
        float a = bm1[j];
        #pragma unroll
        for (int k = 0; k < 64; k++) a += sp[k] * Wm1[k * 100 + j];
        v = fmaxf(a, 0.f) * Wm2[j];
    }
    red[j] = v;
    __syncthreads();
    for (int st = 64; st > 0; st >>= 1) {
        if (j < st) red[j] += red[j + st];
        __syncthreads();
    }
    if (j == 0) outp[b] = red[0] + bm2[0];
}

// ---------------- launch ----------------
extern "C" void kernel_launch(void* const* d_in, const int* in_sizes, int n_in,
                              void* d_out, int out_size) {
    const float* x    = (const float*)d_in[0];
    const float* ea   = (const float*)d_in[1];
    const int*   ei   = (const int*)  d_in[2];
    const int*   batch= (const int*)  d_in[3];
    const float* W1   = (const float*)d_in[4];
    const float* b1   = (const float*)d_in[5];
    const float* W2   = (const float*)d_in[6];
    const float* b2   = (const float*)d_in[7];
    const float* We   = (const float*)d_in[8];
    const float* be   = (const float*)d_in[9];
    const float* Wp   = (const float*)d_in[10];
    const float* bp   = (const float*)d_in[11];
    const float* Wo   = (const float*)d_in[12];
    const float* bo   = (const float*)d_in[13];
    const float* Wl   = (const float*)d_in[14];
    const float* bl   = (const float*)d_in[15];
    const float* gamma= (const float*)d_in[16];
    const float* beta = (const float*)d_in[17];
    const float* Wm1  = (const float*)d_in[18];
    const float* bm1  = (const float*)d_in[19];
    const float* Wm2  = (const float*)d_in[20];
    const float* bm2  = (const float*)d_in[21];

    int N = in_sizes[0] / FDIM;
    int E = in_sizes[1] / 16;

    static const double DEG[17] = {0,1000,2000,4000,8000,16000,24000,20000,12000,
                                   6000,3000,2000,1000,500,300,200,100};
    double snum = 0.0, sden = 0.0;
    for (int i = 0; i < 17; i++) { snum += log((double)i + 1.0) * DEG[i]; sden += DEG[i]; }
    float avg_log = (float)(snum / sden);

    int nb256 = (N + 255) / 256;
    int eb256 = (E + 255) / 256;

    k_init <<<nb256, 256>>>(N);                                           // 1
    k_wowl <<<(832 * FDIM + 255) / 256, 256>>>(Wo, Wl);                   // 2
    k_small<<<(7360 * 32 + 255) / 256, 256>>>(W2, b2, Wp, bp, We, be, bo, Wl, bl); // 3
    k_node <<<nb256, 256>>>(x, W1, b1, N);                                // 4
    k_wprep<<<(3 * 128 * FDIM + 255) / 256, 256>>>();                     // 5
    k_count<<<eb256, 256>>>(ei, E);                                       // 6
    k_scan <<<(N + 1023) / 1024, 1024>>>(N);                              // 7
    k_fill <<<eb256, 256>>>(ei, E);                                       // 8
    k_agg  <<<(N + 7) / 8, 256>>>(ea, N, avg_log);                        // 9
    k_gemm <<<(N + GBM - 1) / GBM, 256>>>(N);                             // 10
    k_bn   <<<1, 64>>>(gamma, beta, N);                                   // 11
    k_pool <<<(N + 1023) / 1024, 256>>>(batch, N);                        // 12
    k_head <<<BGR, 128>>>(Wm1, bm1, Wm2, bm2, (float*)d_out);             // 13
}

// round 13
// speedup vs baseline: 1.1988x; 1.1988x over previous
#include <cuda_runtime.h>
#include <math.h>

#define FDIM 64
#define NMAX 100000
#define EMAX 1600000
#define BGR  64
#define PF 4            // cp.async pipeline depth (power of 2)

typedef unsigned long long ull;

// ---------------- f32x2 helpers ----------------
__device__ __forceinline__ void fma2(ull& acc, ull a, ull b) {
    asm("fma.rn.f32x2 %0, %1, %2, %0;" : "+l"(acc) : "l"(a), "l"(b));
}
__device__ __forceinline__ void add2(ull& acc, ull a) {
    asm("add.rn.f32x2 %0, %1, %0;" : "+l"(acc) : "l"(a));
}
__device__ __forceinline__ ull bpack(float f) {
    ull o; unsigned u = __float_as_uint(f);
    asm("mov.b64 %0, {%1, %1};" : "=l"(o) : "r"(u));
    return o;
}
__device__ __forceinline__ ull pack2(float lo, float hi) {
    ull o;
    asm("mov.b64 %0, {%1, %2};" : "=l"(o) : "r"(__float_as_uint(lo)), "r"(__float_as_uint(hi)));
    return o;
}
__device__ __forceinline__ void unpack2(ull v, float& lo, float& hi) {
    unsigned a, b;
    asm("mov.b64 {%0, %1}, %2;" : "=r"(a), "=r"(b) : "l"(v));
    lo = __uint_as_float(a); hi = __uint_as_float(b);
}
__device__ __forceinline__ void cp_async16(void* smem, const void* gmem) {
    unsigned s = (unsigned)__cvta_generic_to_shared(smem);
    asm volatile("cp.async.cg.shared.global [%0], [%1], 16;" :: "r"(s), "l"(gmem));
}
__device__ __forceinline__ void cp_commit() {
    asm volatile("cp.async.commit_group;");
}
__device__ __forceinline__ void cp_wait() {
    asm volatile("cp.async.wait_group %0;" :: "n"(PF - 1));
}

// ---------------- device scratch ----------------
__device__ __align__(16) float g_C  [NMAX * FDIM];
__device__ __align__(16) float g_ys [NMAX * FDIM];
__device__ __align__(16) float g_zx [NMAX * FDIM];
__device__ __align__(16) float g_agg[(size_t)NMAX * 256];
__device__ float g_amp [NMAX];
__device__ float g_iamp[NMAX];
__device__ __align__(16) float g_out[NMAX * FDIM];
__device__ int   g_cnt [NMAX];
__device__ int   g_offs[NMAX];
__device__ int   g_fill[NMAX];
__device__ int2  g_csr [EMAX];     // (src, edge_id)
__device__ int   g_cursor;
__device__ __align__(16) float g_WoWl[832 * FDIM];
__device__ __align__(16) float g_Md[32 * FDIM], g_Ms[32 * FDIM], g_Mx[32 * FDIM];
__device__ __align__(16) float g_Wec[16 * FDIM];
__device__ float g_Cc[FDIM], g_csv[FDIM], g_cxv[FDIM];
__device__ float g_bnS[FDIM], g_bnQ[FDIM], g_bnA[FDIM], g_bnB[FDIM];
__device__ float g_pool[BGR * FDIM];

// ---------------- init ----------------
__global__ void k_init(int Nn) {
    int i = blockIdx.x * blockDim.x + threadIdx.x;
    if (i < Nn) g_cnt[i] = 0;
    if (i < BGR * FDIM) g_pool[i] = 0.f;
    if (i < FDIM) { g_bnS[i] = 0.f; g_bnQ[i] = 0.f; }
    if (i == 0) g_cursor = 0;
}

// ---------------- WoWl = Wo @ Wl  (832x64) ----------------
__global__ void k_wowl(const float* __restrict__ Wo, const float* __restrict__ Wl) {
    int idx = blockIdx.x * blockDim.x + threadIdx.x;
    if (idx >= 832 * FDIM) return;
    int r = idx >> 6, c = idx & 63;
    float a = 0.f;
    #pragma unroll
    for (int k = 0; k < FDIM; k++) a += Wo[r * FDIM + k] * Wl[k * FDIM + c];
    g_WoWl[idx] = a;
}

// ---------------- small folded-weight precompute (warp per output) ----------------
__global__ void k_small(const float* __restrict__ W2, const float* __restrict__ b2,
                        const float* __restrict__ Wp, const float* __restrict__ bp,
                        const float* __restrict__ We, const float* __restrict__ be,
                        const float* __restrict__ bo, const float* __restrict__ Wl,
                        const float* __restrict__ bl) {
    int gw = (blockIdx.x * blockDim.x + threadIdx.x) >> 5;
    int lane = threadIdx.x & 31;
    if (gw >= 7360) return;
    int k0 = lane, k1 = lane + 32;
    float a = 0.f;
    if (gw < 2048) {
        int i = gw >> 6, c = gw & 63;
        a = W2[i*64+k0]*Wp[k0*64+c] + W2[i*64+k1]*Wp[k1*64+c];
    } else if (gw < 4096) {
        int t = gw - 2048; int i = t >> 6, c = t & 63;
        a = W2[i*64+k0]*Wp[(64+k0)*64+c] + W2[i*64+k1]*Wp[(64+k1)*64+c];
    } else if (gw < 6144) {
        int t = gw - 4096; int i = t >> 6, c = t & 63;
        a = W2[i*64+k0]*g_WoWl[k0*64+c] + W2[i*64+k1]*g_WoWl[k1*64+c];
    } else if (gw < 7168) {
        int t = gw - 6144; int i = t >> 6, c = t & 63;
        a = We[i*64+k0]*Wp[(128+k0)*64+c] + We[i*64+k1]*Wp[(128+k1)*64+c];
    } else if (gw < 7232) {
        int c = gw - 7168;
        a = be[k0]*Wp[(128+k0)*64+c] + b2[k0]*Wp[k0*64+c]
          + be[k1]*Wp[(128+k1)*64+c] + b2[k1]*Wp[k1*64+c];
    } else if (gw < 7296) {
        int c = gw - 7232;
        a = b2[k0]*Wp[(64+k0)*64+c] + b2[k1]*Wp[(64+k1)*64+c];
    } else {
        int c = gw - 7296;
        a = bo[k0]*Wl[k0*64+c] + b2[k0]*g_WoWl[k0*64+c]
          + bo[k1]*Wl[k1*64+c] + b2[k1]*g_WoWl[k1*64+c];
    }
    #pragma unroll
    for (int o = 16; o; o >>= 1) a += __shfl_xor_sync(0xffffffffu, a, o);
    if (lane == 0) {
        if (gw < 2048) g_Md[gw] = a;
        else if (gw < 4096) g_Ms[gw - 2048] = a;
        else if (gw < 6144) g_Mx[gw - 4096] = a;
        else if (gw < 7168) g_Wec[gw - 6144] = a;
        else if (gw < 7232) g_Cc[gw - 7168] = a + bp[gw - 7168];
        else if (gw < 7296) g_csv[gw - 7232] = a;
        else g_cxv[gw - 7296] = a + bl[gw - 7296];
    }
}

// ---------------- node pre-pass (scalar, 79 regs) ----------------
__global__ __launch_bounds__(256) void k_node(const float* __restrict__ x,
                                              const float* __restrict__ W1,
                                              const float* __restrict__ b1, int Nn) {
    __shared__ float sW1[64 * 32];
    __shared__ float sM[3][32 * 64];
    __shared__ float sb1[32];
    __shared__ float sC[3][64];
    int tid = threadIdx.x;
    for (int i = tid; i < 64 * 32; i += 256) sW1[i] = W1[i];
    for (int i = tid; i < 32 * 64; i += 256) {
        sM[0][i] = g_Md[i]; sM[1][i] = g_Ms[i]; sM[2][i] = g_Mx[i];
    }
    if (tid < 32) sb1[tid] = b1[tid];
    if (tid < 64) { sC[0][tid] = g_Cc[tid]; sC[1][tid] = g_csv[tid]; sC[2][tid] = g_cxv[tid]; }
    __syncthreads();
    int n = blockIdx.x * 256 + tid;
    if (n >= Nn) return;

    float xr[64];
    const float4* xp = (const float4*)(x + (size_t)n * 64);
    #pragma unroll
    for (int i = 0; i < 16; i++) {
        float4 v = xp[i];
        xr[4*i] = v.x; xr[4*i+1] = v.y; xr[4*i+2] = v.z; xr[4*i+3] = v.w;
    }
    float t[32];
    #pragma unroll
    for (int j = 0; j < 32; j += 4) {
        float a0 = sb1[j], a1 = sb1[j+1], a2 = sb1[j+2], a3 = sb1[j+3];
        #pragma unroll
        for (int i = 0; i < 64; i++) {
            float xi = xr[i];
            const float* w = &sW1[i * 32 + j];
            a0 += xi * w[0]; a1 += xi * w[1]; a2 += xi * w[2]; a3 += xi * w[3];
        }
        t[j] = fmaxf(a0, 0.f); t[j+1] = fmaxf(a1, 0.f);
        t[j+2] = fmaxf(a2, 0.f); t[j+3] = fmaxf(a3, 0.f);
    }
    float* out0 = g_C  + (size_t)n * 64;
    float* out1 = g_ys + (size_t)n * 64;
    float* out2 = g_zx + (size_t)n * 64;
    #pragma unroll
    for (int m = 0; m < 3; m++) {
        float* op = (m == 0) ? out0 : (m == 1) ? out1 : out2;
        #pragma unroll
        for (int j = 0; j < 64; j += 4) {
            float a0 = sC[m][j], a1 = sC[m][j+1], a2 = sC[m][j+2], a3 = sC[m][j+3];
            #pragma unroll
            for (int i = 0; i < 32; i++) {
                float ti = t[i];
                const float* w = &sM[m][i * 64 + j];
                a0 += ti * w[0]; a1 += ti * w[1]; a2 += ti * w[2]; a3 += ti * w[3];
            }
            float4 v; v.x = a0; v.y = a1; v.z = a2; v.w = a3;
            *(float4*)(op + j) = v;
        }
    }
}

// ---------------- CSR build ----------------
__global__ void k_count(const int* __restrict__ ei, int En) {
    int e = blockIdx.x * blockDim.x + threadIdx.x;
    if (e >= En) return;
    atomicAdd(&g_cnt[ei[En + e]], 1);
}

__global__ void k_scan(int Nn) {
    __shared__ int s[1024];
    __shared__ int base;
    int tid = threadIdx.x;
    int n = blockIdx.x * 1024 + tid;
    int c = (n < Nn) ? g_cnt[n] : 0;
    s[tid] = c;
    __syncthreads();
    for (int d = 1; d < 1024; d <<= 1) {
        int v = (tid >= d) ? s[tid - d] : 0;
        __syncthreads();
        s[tid] += v;
        __syncthreads();
    }
    if (tid == 1023) base = atomicAdd(&g_cursor, s[1023]);
    __syncthreads();
    if (n < Nn) {
        int off = base + s[tid] - c;
        g_offs[n] = off;
        g_fill[n] = off;
    }
}

__global__ void k_fill(const int* __restrict__ ei, int En) {
    int e = blockIdx.x * blockDim.x + threadIdx.x;
    if (e >= En) return;
    int d = ei[En + e];
    int s = ei[e];
    int p = atomicAdd(&g_fill[d], 1);
    g_csr[p] = make_int2(s, e);
}

// ---------------- agg edge body (packed k-pairs) ----------------
__device__ __forceinline__ void agg_body(ulonglong2 u0, ulonglong2 u1,
                                         ulonglong2 u2, ulonglong2 u3,
                                         float cya, float cyb,
                                         const ull* wq0, const ull* wq1,
                                         ull& s2, ull& q2,
                                         float& mn0, float& mx0, float& mn1, float& mx1) {
    ull mA = 0ull, mB = 0ull;
    fma2(mA, u0.x, wq0[0]); fma2(mB, u0.x, wq1[0]);
    fma2(mA, u0.y, wq0[1]); fma2(mB, u0.y, wq1[1]);
    fma2(mA, u1.x, wq0[2]); fma2(mB, u1.x, wq1[2]);
    fma2(mA, u1.y, wq0[3]); fma2(mB, u1.y, wq1[3]);
    fma2(mA, u2.x, wq0[4]); fma2(mB, u2.x, wq1[4]);
    fma2(mA, u2.y, wq0[5]); fma2(mB, u2.y, wq1[5]);
    fma2(mA, u3.x, wq0[6]); fma2(mB, u3.x, wq1[6]);
    fma2(mA, u3.y, wq0[7]); fma2(mB, u3.y, wq1[7]);
    float alo, ahi, blo, bhi;
    unpack2(mA, alo, ahi); unpack2(mB, blo, bhi);
    float m0 = (alo + ahi) + cya;
    float m1 = (blo + bhi) + cyb;
    ull m01 = pack2(m0, m1);
    add2(s2, m01);
    fma2(q2, m01, m01);
    mn0 = fminf(mn0, m0); mx0 = fmaxf(mx0, m0);
    mn1 = fminf(mn1, m1); mx1 = fmaxf(mx1, m1);
}

__device__ __forceinline__ void agg_finish(int n, int d0, ull s2, ull q2,
                                           float mn0, float mx0, float mn1, float mx1,
                                           int lane, float avg_log) {
    float s0, s1, q0, q1;
    unpack2(s2, s0, s1); unpack2(q2, q0, q1);
    float d = (float)((d0 > 1) ? d0 : 1);
    float inv_d = 1.f / d;
    float C0 = g_C[(size_t)n * 64 + lane], C1 = g_C[(size_t)n * 64 + 32 + lane];
    float mu0 = s0 * inv_d, mu1 = s1 * inv_d;
    float sd0 = sqrtf(fmaxf(q0 * inv_d - mu0 * mu0, 0.f) + 1e-5f);
    float sd1 = sqrtf(fmaxf(q1 * inv_d - mu1 * mu1, 0.f) + 1e-5f);
    float mean0, mean1;
    if (d0 > 0) {
        mean0 = mu0 + C0; mn0 += C0; mx0 += C0;
        mean1 = mu1 + C1; mn1 += C1; mx1 += C1;
    } else {
        mean0 = 0.f; mn0 = 0.f; mx0 = 0.f;
        mean1 = 0.f; mn1 = 0.f; mx1 = 0.f;
    }
    float amp = logf(d + 1.f) / avg_log;
    float iamp = 1.f / amp;
    float* A = g_agg + (size_t)n * 256;
    A[lane]       = mean0; A[32 + lane]  = mean1;
    A[64 + lane]  = mn0;   A[96 + lane]  = mn1;
    A[128 + lane] = mx0;   A[160 + lane] = mx1;
    A[192 + lane] = sd0;   A[224 + lane] = sd1;
    if (lane == 0) { g_amp[n] = amp; g_iamp[n] = iamp; }
}

// ---------------- aggregation: warp per node, cp.async depth-4 ea pipeline ------
__global__ __launch_bounds__(256) void k_agg(const float* __restrict__ ea, int Nn, float avg_log) {
    __shared__ __align__(16) float sEA[8][PF][16];
    int lane = threadIdx.x & 31;
    int w = threadIdx.x >> 5;
    int n = (blockIdx.x * 256 + threadIdx.x) >> 5;
    if (n >= Nn) return;

    ull wq0[8], wq1[8];
    #pragma unroll
    for (int kp = 0; kp < 8; kp++) {
        wq0[kp] = pack2(g_Wec[(2*kp)*64 + lane],      g_Wec[(2*kp+1)*64 + lane]);
        wq1[kp] = pack2(g_Wec[(2*kp)*64 + 32 + lane], g_Wec[(2*kp+1)*64 + 32 + lane]);
    }
    int off = g_offs[n];
    int d0 = g_cnt[n];
    ull s2 = 0ull, q2 = 0ull;
    float mn0 = 3.4e38f, mn1 = 3.4e38f, mx0 = -3.4e38f, mx1 = -3.4e38f;

    // prologue: stage first PF edges' ea into smem
    #pragma unroll
    for (int j = 0; j < PF; j++) {
        if (j < d0) {
            int eid = g_csr[off + j].y;
            if (lane < 4)
                cp_async16(&sEA[w][j][lane * 4], ea + (size_t)eid * 16 + lane * 4);
        }
        cp_commit();
    }

    if (d0 > 0) {
        int2 se = g_csr[off];
        const float* yp = g_ys + (size_t)se.x * 64;
        float pya = yp[lane], pyb = yp[32 + lane];

        for (int i = 0; i < d0; i++) {
            float cya = pya, cyb = pyb;
            if (i + 1 < d0) {
                int2 ne = g_csr[off + i + 1];
                const float* yq = g_ys + (size_t)ne.x * 64;
                pya = yq[lane]; pyb = yq[32 + lane];
            }
            cp_wait();
            __syncwarp();
            const ulonglong2* p = (const ulonglong2*)sEA[w][i & (PF - 1)];
            ulonglong2 u0 = p[0], u1 = p[1], u2 = p[2], u3 = p[3];
            __syncwarp();
            // refill this stage with edge i+PF
            int j = i + PF;
            if (j < d0) {
                int eid = g_csr[off + j].y;
                if (lane < 4)
                    cp_async16(&sEA[w][i & (PF - 1)][lane * 4], ea + (size_t)eid * 16 + lane * 4);
            }
            cp_commit();
            agg_body(u0, u1, u2, u3, cya, cyb, wq0, wq1, s2, q2, mn0, mx0, mn1, mx1);
        }
    }
    agg_finish(n, d0, s2, q2, mn0, mx0, mn1, mx1, lane, avg_log);
}

// ---------------- big GEMM: 128 thr, 64x64 tile, 8-row thread tile ----------------
#define GBM 64
#define GBK 32
__global__ __launch_bounds__(128) void k_gemm(int Nn) {
    __shared__ __align__(16) float sA[GBM * GBK];
    __shared__ __align__(16) float sW[3][GBK * 64];
    __shared__ float sS[64], sQ[64];
    int tid = threadIdx.x;
    if (tid < 64) { sS[tid] = 0.f; sQ[tid] = 0.f; }
    int bm = blockIdx.x * GBM;
    int tr8 = (tid >> 4) << 3;
    int c4  = (tid & 15) << 2;

    ull acc[3][8][2];
    #pragma unroll
    for (int m = 0; m < 3; m++)
        #pragma unroll
        for (int i = 0; i < 8; i++) { acc[m][i][0] = 0ull; acc[m][i][1] = 0ull; }

    const float* Wbase = g_WoWl + 64 * 64;
    for (int k0 = 0; k0 < 256; k0 += GBK) {
        #pragma unroll
        for (int l = 0; l < 4; l++) {
            int lin = tid + 128 * l;
            int r = lin >> 3, kq = (lin & 7) << 2;
            int row = bm + r;
            float4 vz = make_float4(0.f, 0.f, 0.f, 0.f);
            float4 vv = (row < Nn) ? *(const float4*)(g_agg + (size_t)row * 256 + k0 + kq) : vz;
            *(float4*)&sA[r * GBK + kq] = vv;
        }
        #pragma unroll
        for (int l = 0; l < 12; l++) {
            int lin = tid + 128 * l;
            int m = lin >> 9, t2 = lin & 511;
            int k = t2 >> 4, cq = (t2 & 15) << 2;
            *(float4*)&sW[m][k * 64 + cq] =
                *(const float4*)(Wbase + (size_t)(m * 256 + k0 + k) * 64 + cq);
        }
        __syncthreads();
        #pragma unroll
        for (int kk = 0; kk < GBK; kk++) {
            ulonglong2 w0 = *(const ulonglong2*)&sW[0][kk * 64 + c4];
            ulonglong2 w1 = *(const ulonglong2*)&sW[1][kk * 64 + c4];
            ulonglong2 w2 = *(const ulonglong2*)&sW[2][kk * 64 + c4];
            #pragma unroll
            for (int i = 0; i < 8; i++) {
                ull a = bpack(sA[(tr8 + i) * GBK + kk]);
                fma2(acc[0][i][0], a, w0.x); fma2(acc[0][i][1], a, w0.y);
                fma2(acc[1][i][0], a, w1.x); fma2(acc[1][i][1], a, w1.y);
                fma2(acc[2][i][0], a, w2.x); fma2(acc[2][i][1], a, w2.y);
            }
        }
        __syncthreads();
    }

    float lS[4] = {0.f, 0.f, 0.f, 0.f};
    float lQ[4] = {0.f, 0.f, 0.f, 0.f};
    #pragma unroll
    for (int i = 0; i < 8; i++) {
        int row = bm + tr8 + i;
        if (row < Nn) {
            float amp = g_amp[row], ia = g_iamp[row];
            float4 z = *(const float4*)(g_zx + (size_t)row * 64 + c4);
            float o[4];
            #pragma unroll
            for (int j = 0; j < 2; j++) {
                float A0, A1, B0, B1, Cv0, Cv1;
                unpack2(acc[0][i][j], A0, A1);
                unpack2(acc[1][i][j], B0, B1);
                unpack2(acc[2][i][j], Cv0, Cv1);
                o[2 * j]     = A0 + amp * B0 + ia * Cv0;
                o[2 * j + 1] = A1 + amp * B1 + ia * Cv1;
            }
            o[0] += z.x; o[1] += z.y; o[2] += z.z; o[3] += z.w;
            float4 ov; ov.x = o[0]; ov.y = o[1]; ov.z = o[2]; ov.w = o[3];
            *(float4*)(g_out + (size_t)row * 64 + c4) = ov;
            #pragma unroll
            for (int j = 0; j < 4; j++) { lS[j] += o[j]; lQ[j] += o[j] * o[j]; }
        }
    }
    #pragma unroll
    for (int j = 0; j < 4; j++) {
        atomicAdd(&sS[c4 + j], lS[j]);
        atomicAdd(&sQ[c4 + j], lQ[j]);
    }
    __syncthreads();
    if (tid < 64) {
        atomicAdd(&g_bnS[tid], sS[tid]);
        atomicAdd(&g_bnQ[tid], sQ[tid]);
    }
}

// ---------------- BN finalize ----------------
__global__ void k_bn(const float* __restrict__ gamma, const float* __restrict__ beta, int Nn) {
    int f = threadIdx.x;
    if (f >= 64) return;
    float inv_n = 1.f / (float)Nn;
    float mu = g_bnS[f] * inv_n;
    float var = g_bnQ[f] * inv_n - mu * mu;
    float sc = gamma[f] * rsqrtf(var + 1e-5f);
    g_bnA[f] = sc;
    g_bnB[f] = beta[f] - mu * sc;
}

// ---------------- pooling ----------------
__global__ void k_pool(const int* __restrict__ batch, int Nn) {
    int f = threadIdx.x & 63;
    int g = threadIdx.x >> 6;
    int n0 = blockIdx.x * 1024;
    float sc = g_bnA[f], sh = g_bnB[f];
    float acc = 0.f;
    int cur = -1;
    for (int i = g; i < 1024; i += 4) {
        int n = n0 + i;
        if (n >= Nn) break;
        int b = batch[n];
        float v = fmaxf(g_out[(size_t)n * 64 + f] * sc + sh, 0.f);
        if (b != cur) {
            if (cur >= 0) atomicAdd(&g_pool[cur * 64 + f], acc);
            cur = b; acc = v;
        } else {
            acc += v;
        }
    }
    if (cur >= 0) atomicAdd(&g_pool[cur * 64 + f], acc);
}

// ---------------- head MLP ----------------
__global__ void k_head(const float* __restrict__ Wm1, const float* __restrict__ bm1,
                       const float* __restrict__ Wm2, const float* __restrict__ bm2,
                       float* __restrict__ outp) {
    __shared__ float sp[64];
    __shared__ float red[128];
    int b = blockIdx.x, j = threadIdx.x;
    if (j < 64) sp[j] = g_pool[b * 64 + j];
    __syncthreads();
    float v = 0.f;
    if (j < 100) {
        float a = bm1[j];
        #pragma unroll
        for (int k = 0; k < 64; k++) a += sp[k] * Wm1[k * 100 + j];
        v = fmaxf(a, 0.f) * Wm2[j];
    }
    red[j] = v;
    __syncthreads();
    for (int st = 64; st > 0; st >>= 1) {
        if (j < st) red[j] += red[j + st];
        __syncthreads();
    }
    if (j == 0) outp[b] = red[0] + bm2[0];
}

// ---------------- launch ----------------
extern "C" void kernel_launch(void* const* d_in, const int* in_sizes, int n_in,
                              void* d_out, int out_size) {
    const float* x    = (const float*)d_in[0];
    const float* ea   = (const float*)d_in[1];
    const int*   ei   = (const int*)  d_in[2];
    const int*   batch= (const int*)  d_in[3];
    const float* W1   = (const float*)d_in[4];
    const float* b1   = (const float*)d_in[5];
    const float* W2   = (const float*)d_in[6];
    const float* b2   = (const float*)d_in[7];
    const float* We   = (const float*)d_in[8];
    const float* be   = (const float*)d_in[9];
    const float* Wp   = (const float*)d_in[10];
    const float* bp   = (const float*)d_in[11];
    const float* Wo   = (const float*)d_in[12];
    const float* bo   = (const float*)d_in[13];
    const float* Wl   = (const float*)d_in[14];
    const float* bl   = (const float*)d_in[15];
    const float* gamma= (const float*)d_in[16];
    const float* beta = (const float*)d_in[17];
    const float* Wm1  = (const float*)d_in[18];
    const float* bm1  = (const float*)d_in[19];
    const float* Wm2  = (const float*)d_in[20];
    const float* bm2  = (const float*)d_in[21];

    int N = in_sizes[0] / FDIM;
    int E = in_sizes[1] / 16;

    static const double DEG[17] = {0,1000,2000,4000,8000,16000,24000,20000,12000,
                                   6000,3000,2000,1000,500,300,200,100};
    double snum = 0.0, sden = 0.0;
    for (int i = 0; i < 17; i++) { snum += log((double)i + 1.0) * DEG[i]; sden += DEG[i]; }
    float avg_log = (float)(snum / sden);

    int nb256 = (N + 255) / 256;
    int eb256 = (E + 255) / 256;

    k_init <<<nb256, 256>>>(N);                                           // 1
    k_wowl <<<(832 * FDIM + 255) / 256, 256>>>(Wo, Wl);                   // 2
    k_small<<<(7360 * 32 + 255) / 256, 256>>>(W2, b2, Wp, bp, We, be, bo, Wl, bl); // 3
    k_node <<<nb256, 256>>>(x, W1, b1, N);                                // 4
    k_count<<<eb256, 256>>>(ei, E);                                       // 5
    k_scan <<<(N + 1023) / 1024, 1024>>>(N);                              // 6
    k_fill <<<eb256, 256>>>(ei, E);                                       // 7
    k_agg  <<<(N + 7) / 8, 256>>>(ea, N, avg_log);                        // 8
    k_gemm <<<(N + GBM - 1) / GBM, 128>>>(N);                             // 9
    k_bn   <<<1, 64>>>(gamma, beta, N);                                   // 10
    k_pool <<<(N + 1023) / 1024, 256>>>(batch, N);                        // 11
    k_head <<<BGR, 128>>>(Wm1, bm1, Wm2, bm2, (float*)d_out);             // 12
}

// round 14
// speedup vs baseline: 1.4452x; 1.2055x over previous
#include <cuda_runtime.h>
#include <math.h>

#define FDIM 64
#define NMAX 100000
#define EMAX 1600000
#define BGR  64
#define PF 4            // cp.async pipeline depth (power of 2)

typedef unsigned long long ull;

// ---------------- f32x2 helpers ----------------
__device__ __forceinline__ void fma2(ull& acc, ull a, ull b) {
    asm("fma.rn.f32x2 %0, %1, %2, %0;" : "+l"(acc) : "l"(a), "l"(b));
}
__device__ __forceinline__ void add2(ull& acc, ull a) {
    asm("add.rn.f32x2 %0, %1, %0;" : "+l"(acc) : "l"(a));
}
__device__ __forceinline__ ull bpack(float f) {
    ull o; unsigned u = __float_as_uint(f);
    asm("mov.b64 %0, {%1, %1};" : "=l"(o) : "r"(u));
    return o;
}
__device__ __forceinline__ ull pack2(float lo, float hi) {
    ull o;
    asm("mov.b64 %0, {%1, %2};" : "=l"(o) : "r"(__float_as_uint(lo)), "r"(__float_as_uint(hi)));
    return o;
}
__device__ __forceinline__ void unpack2(ull v, float& lo, float& hi) {
    unsigned a, b;
    asm("mov.b64 {%0, %1}, %2;" : "=r"(a), "=r"(b) : "l"(v));
    lo = __uint_as_float(a); hi = __uint_as_float(b);
}
__device__ __forceinline__ void cp_async16(void* smem, const void* gmem) {
    unsigned s = (unsigned)__cvta_generic_to_shared(smem);
    asm volatile("cp.async.cg.shared.global [%0], [%1], 16;" :: "r"(s), "l"(gmem));
}
__device__ __forceinline__ void cp_commit() {
    asm volatile("cp.async.commit_group;");
}
__device__ __forceinline__ void cp_wait() {
    asm volatile("cp.async.wait_group %0;" :: "n"(PF - 1));
}

// ---------------- device scratch ----------------
__device__ __align__(16) float g_C  [NMAX * FDIM];
__device__ __align__(16) float g_ys [NMAX * FDIM];
__device__ __align__(16) float g_zx [NMAX * FDIM];
__device__ __align__(16) float g_agg[(size_t)NMAX * 256];
__device__ float g_amp [NMAX];
__device__ float g_iamp[NMAX];
__device__ __align__(16) float g_out[NMAX * FDIM];
__device__ int   g_cnt [NMAX];
__device__ int   g_offs[NMAX];
__device__ int   g_fill[NMAX];
__device__ int2  g_csr [EMAX];     // (src, edge_id)
__device__ int   g_cursor;
__device__ __align__(16) float g_WoWl[832 * FDIM];
__device__ __align__(16) float g_Md[32 * FDIM], g_Ms[32 * FDIM], g_Mx[32 * FDIM];
__device__ __align__(16) float g_Wec[16 * FDIM];
__device__ float g_Cc[FDIM], g_csv[FDIM], g_cxv[FDIM];
__device__ float g_bnS[FDIM], g_bnQ[FDIM], g_bnA[FDIM], g_bnB[FDIM];
__device__ float g_pool[BGR * FDIM];

// ---------------- init ----------------
__global__ void k_init(int Nn) {
    int i = blockIdx.x * blockDim.x + threadIdx.x;
    if (i < Nn) g_cnt[i] = 0;
    if (i < BGR * FDIM) g_pool[i] = 0.f;
    if (i < FDIM) { g_bnS[i] = 0.f; g_bnQ[i] = 0.f; }
    if (i == 0) g_cursor = 0;
}

// ---------------- WoWl = Wo @ Wl  (832x64) ----------------
__global__ void k_wowl(const float* __restrict__ Wo, const float* __restrict__ Wl) {
    int idx = blockIdx.x * blockDim.x + threadIdx.x;
    if (idx >= 832 * FDIM) return;
    int r = idx >> 6, c = idx & 63;
    float a = 0.f;
    #pragma unroll
    for (int k = 0; k < FDIM; k++) a += Wo[r * FDIM + k] * Wl[k * FDIM + c];
    g_WoWl[idx] = a;
}

// ---------------- small folded-weight precompute (warp per output) ----------------
__global__ void k_small(const float* __restrict__ W2, const float* __restrict__ b2,
                        const float* __restrict__ Wp, const float* __restrict__ bp,
                        const float* __restrict__ We, const float* __restrict__ be,
                        const float* __restrict__ bo, const float* __restrict__ Wl,
                        const float* __restrict__ bl) {
    int gw = (blockIdx.x * blockDim.x + threadIdx.x) >> 5;
    int lane = threadIdx.x & 31;
    if (gw >= 7360) return;
    int k0 = lane, k1 = lane + 32;
    float a = 0.f;
    if (gw < 2048) {
        int i = gw >> 6, c = gw & 63;
        a = W2[i*64+k0]*Wp[k0*64+c] + W2[i*64+k1]*Wp[k1*64+c];
    } else if (gw < 4096) {
        int t = gw - 2048; int i = t >> 6, c = t & 63;
        a = W2[i*64+k0]*Wp[(64+k0)*64+c] + W2[i*64+k1]*Wp[(64+k1)*64+c];
    } else if (gw < 6144) {
        int t = gw - 4096; int i = t >> 6, c = t & 63;
        a = W2[i*64+k0]*g_WoWl[k0*64+c] + W2[i*64+k1]*g_WoWl[k1*64+c];
    } else if (gw < 7168) {
        int t = gw - 6144; int i = t >> 6, c = t & 63;
        a = We[i*64+k0]*Wp[(128+k0)*64+c] + We[i*64+k1]*Wp[(128+k1)*64+c];
    } else if (gw < 7232) {
        int c = gw - 7168;
        a = be[k0]*Wp[(128+k0)*64+c] + b2[k0]*Wp[k0*64+c]
          + be[k1]*Wp[(128+k1)*64+c] + b2[k1]*Wp[k1*64+c];
    } else if (gw < 7296) {
        int c = gw - 7232;
        a = b2[k0]*Wp[(64+k0)*64+c] + b2[k1]*Wp[(64+k1)*64+c];
    } else {
        int c = gw - 7296;
        a = bo[k0]*Wl[k0*64+c] + b2[k0]*g_WoWl[k0*64+c]
          + bo[k1]*Wl[k1*64+c] + b2[k1]*g_WoWl[k1*64+c];
    }
    #pragma unroll
    for (int o = 16; o; o >>= 1) a += __shfl_xor_sync(0xffffffffu, a, o);
    if (lane == 0) {
        if (gw < 2048) g_Md[gw] = a;
        else if (gw < 4096) g_Ms[gw - 2048] = a;
        else if (gw < 6144) g_Mx[gw - 4096] = a;
        else if (gw < 7168) g_Wec[gw - 6144] = a;
        else if (gw < 7232) g_Cc[gw - 7168] = a + bp[gw - 7168];
        else if (gw < 7296) g_csv[gw - 7232] = a;
        else g_cxv[gw - 7296] = a + bl[gw - 7296];
    }
}

// ---------------- node pre-pass (scalar, 79 regs) ----------------
__global__ __launch_bounds__(256) void k_node(const float* __restrict__ x,
                                              const float* __restrict__ W1,
                                              const float* __restrict__ b1, int Nn) {
    __shared__ float sW1[64 * 32];
    __shared__ float sM[3][32 * 64];
    __shared__ float sb1[32];
    __shared__ float sC[3][64];
    int tid = threadIdx.x;
    for (int i = tid; i < 64 * 32; i += 256) sW1[i] = W1[i];
    for (int i = tid; i < 32 * 64; i += 256) {
        sM[0][i] = g_Md[i]; sM[1][i] = g_Ms[i]; sM[2][i] = g_Mx[i];
    }
    if (tid < 32) sb1[tid] = b1[tid];
    if (tid < 64) { sC[0][tid] = g_Cc[tid]; sC[1][tid] = g_csv[tid]; sC[2][tid] = g_cxv[tid]; }
    __syncthreads();
    int n = blockIdx.x * 256 + tid;
    if (n >= Nn) return;

    float xr[64];
    const float4* xp = (const float4*)(x + (size_t)n * 64);
    #pragma unroll
    for (int i = 0; i < 16; i++) {
        float4 v = xp[i];
        xr[4*i] = v.x; xr[4*i+1] = v.y; xr[4*i+2] = v.z; xr[4*i+3] = v.w;
    }
    float t[32];
    #pragma unroll
    for (int j = 0; j < 32; j += 4) {
        float a0 = sb1[j], a1 = sb1[j+1], a2 = sb1[j+2], a3 = sb1[j+3];
        #pragma unroll
        for (int i = 0; i < 64; i++) {
            float xi = xr[i];
            const float* w = &sW1[i * 32 + j];
            a0 += xi * w[0]; a1 += xi * w[1]; a2 += xi * w[2]; a3 += xi * w[3];
        }
        t[j] = fmaxf(a0, 0.f); t[j+1] = fmaxf(a1, 0.f);
        t[j+2] = fmaxf(a2, 0.f); t[j+3] = fmaxf(a3, 0.f);
    }
    float* out0 = g_C  + (size_t)n * 64;
    float* out1 = g_ys + (size_t)n * 64;
    float* out2 = g_zx + (size_t)n * 64;
    #pragma unroll
    for (int m = 0; m < 3; m++) {
        float* op = (m == 0) ? out0 : (m == 1) ? out1 : out2;
        #pragma unroll
        for (int j = 0; j < 64; j += 4) {
            float a0 = sC[m][j], a1 = sC[m][j+1], a2 = sC[m][j+2], a3 = sC[m][j+3];
            #pragma unroll
            for (int i = 0; i < 32; i++) {
                float ti = t[i];
                const float* w = &sM[m][i * 64 + j];
                a0 += ti * w[0]; a1 += ti * w[1]; a2 += ti * w[2]; a3 += ti * w[3];
            }
            float4 v; v.x = a0; v.y = a1; v.z = a2; v.w = a3;
            *(float4*)(op + j) = v;
        }
    }
}

// ---------------- CSR build ----------------
__global__ void k_count(const int* __restrict__ ei, int En) {
    int e = blockIdx.x * blockDim.x + threadIdx.x;
    if (e >= En) return;
    atomicAdd(&g_cnt[ei[En + e]], 1);
}

__global__ void k_scan(int Nn) {
    __shared__ int s[1024];
    __shared__ int base;
    int tid = threadIdx.x;
    int n = blockIdx.x * 1024 + tid;
    int c = (n < Nn) ? g_cnt[n] : 0;
    s[tid] = c;
    __syncthreads();
    for (int d = 1; d < 1024; d <<= 1) {
        int v = (tid >= d) ? s[tid - d] : 0;
        __syncthreads();
        s[tid] += v;
        __syncthreads();
    }
    if (tid == 1023) base = atomicAdd(&g_cursor, s[1023]);
    __syncthreads();
    if (n < Nn) {
        int off = base + s[tid] - c;
        g_offs[n] = off;
        g_fill[n] = off;
    }
}

__global__ void k_fill(const int* __restrict__ ei, int En) {
    int e = blockIdx.x * blockDim.x + threadIdx.x;
    if (e >= En) return;
    int d = ei[En + e];
    int s = ei[e];
    int p = atomicAdd(&g_fill[d], 1);
    g_csr[p] = make_int2(s, e);
}

// ---------------- agg edge body (packed k-pairs) ----------------
__device__ __forceinline__ void agg_body(ulonglong2 u0, ulonglong2 u1,
                                         ulonglong2 u2, ulonglong2 u3,
                                         float cya, float cyb,
                                         const ull* wq0, const ull* wq1,
                                         ull& s2, ull& q2,
                                         float& mn0, float& mx0, float& mn1, float& mx1) {
    ull mA = 0ull, mB = 0ull;
    fma2(mA, u0.x, wq0[0]); fma2(mB, u0.x, wq1[0]);
    fma2(mA, u0.y, wq0[1]); fma2(mB, u0.y, wq1[1]);
    fma2(mA, u1.x, wq0[2]); fma2(mB, u1.x, wq1[2]);
    fma2(mA, u1.y, wq0[3]); fma2(mB, u1.y, wq1[3]);
    fma2(mA, u2.x, wq0[4]); fma2(mB, u2.x, wq1[4]);
    fma2(mA, u2.y, wq0[5]); fma2(mB, u2.y, wq1[5]);
    fma2(mA, u3.x, wq0[6]); fma2(mB, u3.x, wq1[6]);
    fma2(mA, u3.y, wq0[7]); fma2(mB, u3.y, wq1[7]);
    float alo, ahi, blo, bhi;
    unpack2(mA, alo, ahi); unpack2(mB, blo, bhi);
    float m0 = (alo + ahi) + cya;
    float m1 = (blo + bhi) + cyb;
    ull m01 = pack2(m0, m1);
    add2(s2, m01);
    fma2(q2, m01, m01);
    mn0 = fminf(mn0, m0); mx0 = fmaxf(mx0, m0);
    mn1 = fminf(mn1, m1); mx1 = fmaxf(mx1, m1);
}

__device__ __forceinline__ void agg_finish(int n, int d0, ull s2, ull q2,
                                           float mn0, float mx0, float mn1, float mx1,
                                           int lane, float avg_log) {
    float s0, s1, q0, q1;
    unpack2(s2, s0, s1); unpack2(q2, q0, q1);
    float d = (float)((d0 > 1) ? d0 : 1);
    float inv_d = 1.f / d;
    float C0 = g_C[(size_t)n * 64 + lane], C1 = g_C[(size_t)n * 64 + 32 + lane];
    float mu0 = s0 * inv_d, mu1 = s1 * inv_d;
    float sd0 = sqrtf(fmaxf(q0 * inv_d - mu0 * mu0, 0.f) + 1e-5f);
    float sd1 = sqrtf(fmaxf(q1 * inv_d - mu1 * mu1, 0.f) + 1e-5f);
    float mean0, mean1;
    if (d0 > 0) {
        mean0 = mu0 + C0; mn0 += C0; mx0 += C0;
        mean1 = mu1 + C1; mn1 += C1; mx1 += C1;
    } else {
        mean0 = 0.f; mn0 = 0.f; mx0 = 0.f;
        mean1 = 0.f; mn1 = 0.f; mx1 = 0.f;
    }
    float amp = logf(d + 1.f) / avg_log;
    float iamp = 1.f / amp;
    float* A = g_agg + (size_t)n * 256;
    A[lane]       = mean0; A[32 + lane]  = mean1;
    A[64 + lane]  = mn0;   A[96 + lane]  = mn1;
    A[128 + lane] = mx0;   A[160 + lane] = mx1;
    A[192 + lane] = sd0;   A[224 + lane] = sd1;
    if (lane == 0) { g_amp[n] = amp; g_iamp[n] = iamp; }
}

// ---- aggregation: warp per node, cp.async depth-4 pipeline on BOTH ea and ys ----
__global__ __launch_bounds__(256) void k_agg(const float* __restrict__ ea, int Nn, float avg_log) {
    __shared__ __align__(16) float sEA[8][PF][16];
    __shared__ __align__(16) float sYS[8][PF][64];
    int lane = threadIdx.x & 31;
    int w = threadIdx.x >> 5;
    int n = (blockIdx.x * 256 + threadIdx.x) >> 5;
    if (n >= Nn) return;

    ull wq0[8], wq1[8];
    #pragma unroll
    for (int kp = 0; kp < 8; kp++) {
        wq0[kp] = pack2(g_Wec[(2*kp)*64 + lane],      g_Wec[(2*kp+1)*64 + lane]);
        wq1[kp] = pack2(g_Wec[(2*kp)*64 + 32 + lane], g_Wec[(2*kp+1)*64 + 32 + lane]);
    }
    int off = g_offs[n];
    int d0 = g_cnt[n];
    ull s2 = 0ull, q2 = 0ull;
    float mn0 = 3.4e38f, mn1 = 3.4e38f, mx0 = -3.4e38f, mx1 = -3.4e38f;

    // prologue: stage first PF edges (ys: lanes 0-15, ea: lanes 16-19)
    #pragma unroll
    for (int j = 0; j < PF; j++) {
        if (j < d0) {
            int2 se = g_csr[off + j];
            if (lane < 16)
                cp_async16(&sYS[w][j][lane * 4], g_ys + (size_t)se.x * 64 + lane * 4);
            else if (lane < 20)
                cp_async16(&sEA[w][j][(lane - 16) * 4], ea + (size_t)se.y * 16 + (lane - 16) * 4);
        }
        cp_commit();
    }

    for (int i = 0; i < d0; i++) {
        cp_wait();
        __syncwarp();
        int st = i & (PF - 1);
        float cya = sYS[w][st][lane];
        float cyb = sYS[w][st][32 + lane];
        const ulonglong2* p = (const ulonglong2*)sEA[w][st];
        ulonglong2 u0 = p[0], u1 = p[1], u2 = p[2], u3 = p[3];
        __syncwarp();
        // refill this stage with edge i+PF
        int j = i + PF;
        if (j < d0) {
            int2 se = g_csr[off + j];
            if (lane < 16)
                cp_async16(&sYS[w][st][lane * 4], g_ys + (size_t)se.x * 64 + lane * 4);
            else if (lane < 20)
                cp_async16(&sEA[w][st][(lane - 16) * 4], ea + (size_t)se.y * 16 + (lane - 16) * 4);
        }
        cp_commit();
        agg_body(u0, u1, u2, u3, cya, cyb, wq0, wq1, s2, q2, mn0, mx0, mn1, mx1);
    }
    agg_finish(n, d0, s2, q2, mn0, mx0, mn1, mx1, lane, avg_log);
}

// ---------------- big GEMM: 128 thr, 64x64 tile, 8-row thread tile ----------------
#define GBM 64
#define GBK 32
__global__ __launch_bounds__(128) void k_gemm(int Nn) {
    __shared__ __align__(16) float sA[GBM * GBK];
    __shared__ __align__(16) float sW[3][GBK * 64];
    __shared__ float sS[64], sQ[64];
    int tid = threadIdx.x;
    if (tid < 64) { sS[tid] = 0.f; sQ[tid] = 0.f; }
    int bm = blockIdx.x * GBM;
    int tr8 = (tid >> 4) << 3;
    int c4  = (tid & 15) << 2;

    ull acc[3][8][2];
    #pragma unroll
    for (int m = 0; m < 3; m++)
        #pragma unroll
        for (int i = 0; i < 8; i++) { acc[m][i][0] = 0ull; acc[m][i][1] = 0ull; }

    const float* Wbase = g_WoWl + 64 * 64;
    for (int k0 = 0; k0 < 256; k0 += GBK) {
        #pragma unroll
        for (int l = 0; l < 4; l++) {
            int lin = tid + 128 * l;
            int r = lin >> 3, kq = (lin & 7) << 2;
            int row = bm + r;
            float4 vz = make_float4(0.f, 0.f, 0.f, 0.f);
            float4 vv = (row < Nn) ? *(const float4*)(g_agg + (size_t)row * 256 + k0 + kq) : vz;
            *(float4*)&sA[r * GBK + kq] = vv;
        }
        #pragma unroll
        for (int l = 0; l < 12; l++) {
            int lin = tid + 128 * l;
            int m = lin >> 9, t2 = lin & 511;
            int k = t2 >> 4, cq = (t2 & 15) << 2;
            *(float4*)&sW[m][k * 64 + cq] =
                *(const float4*)(Wbase + (size_t)(m * 256 + k0 + k) * 64 + cq);
        }
        __syncthreads();
        #pragma unroll
        for (int kk = 0; kk < GBK; kk++) {
            ulonglong2 w0 = *(const ulonglong2*)&sW[0][kk * 64 + c4];
            ulonglong2 w1 = *(const ulonglong2*)&sW[1][kk * 64 + c4];
            ulonglong2 w2 = *(const ulonglong2*)&sW[2][kk * 64 + c4];
            #pragma unroll
            for (int i = 0; i < 8; i++) {
                ull a = bpack(sA[(tr8 + i) * GBK + kk]);
                fma2(acc[0][i][0], a, w0.x); fma2(acc[0][i][1], a, w0.y);
                fma2(acc[1][i][0], a, w1.x); fma2(acc[1][i][1], a, w1.y);
                fma2(acc[2][i][0], a, w2.x); fma2(acc[2][i][1], a, w2.y);
            }
        }
        __syncthreads();
    }

    float lS[4] = {0.f, 0.f, 0.f, 0.f};
    float lQ[4] = {0.f, 0.f, 0.f, 0.f};
    #pragma unroll
    for (int i = 0; i < 8; i++) {
        int row = bm + tr8 + i;
        if (row < Nn) {
            float amp = g_amp[row], ia = g_iamp[row];
            float4 z = *(const float4*)(g_zx + (size_t)row * 64 + c4);
            float o[4];
            #pragma unroll
            for (int j = 0; j < 2; j++) {
                float A0, A1, B0, B1, Cv0, Cv1;
                unpack2(acc[0][i][j], A0, A1);
                unpack2(acc[1][i][j], B0, B1);
                unpack2(acc[2][i][j], Cv0, Cv1);
                o[2 * j]     = A0 + amp * B0 + ia * Cv0;
                o[2 * j + 1] = A1 + amp * B1 + ia * Cv1;
            }
            o[0] += z.x; o[1] += z.y; o[2] += z.z; o[3] += z.w;
            float4 ov; ov.x = o[0]; ov.y = o[1]; ov.z = o[2]; ov.w = o[3];
            *(float4*)(g_out + (size_t)row * 64 + c4) = ov;
            #pragma unroll
            for (int j = 0; j < 4; j++) { lS[j] += o[j]; lQ[j] += o[j] * o[j]; }
        }
    }
    #pragma unroll
    for (int j = 0; j < 4; j++) {
        atomicAdd(&sS[c4 + j], lS[j]);
        atomicAdd(&sQ[c4 + j], lQ[j]);
    }
    __syncthreads();
    if (tid < 64) {
        atomicAdd(&g_bnS[tid], sS[tid]);
        atomicAdd(&g_bnQ[tid], sQ[tid]);
    }
}

// ---------------- BN finalize ----------------
__global__ void k_bn(const float* __restrict__ gamma, const float* __restrict__ beta, int Nn) {
    int f = threadIdx.x;
    if (f >= 64) return;
    float inv_n = 1.f / (float)Nn;
    float mu = g_bnS[f] * inv_n;
    float var = g_bnQ[f] * inv_n - mu * mu;
    float sc = gamma[f] * rsqrtf(var + 1e-5f);
    g_bnA[f] = sc;
    g_bnB[f] = beta[f] - mu * sc;
}

// ---------------- pooling ----------------
__global__ void k_pool(const int* __restrict__ batch, int Nn) {
    int f = threadIdx.x & 63;
    int g = threadIdx.x >> 6;
    int n0 = blockIdx.x * 1024;
    float sc = g_bnA[f], sh = g_bnB[f];
    float acc = 0.f;
    int cur = -1;
    for (int i = g; i < 1024; i += 4) {
        int n = n0 + i;
        if (n >= Nn) break;
        int b = batch[n];
        float v = fmaxf(g_out[(size_t)n * 64 + f] * sc + sh, 0.f);
        if (b != cur) {
            if (cur >= 0) atomicAdd(&g_pool[cur * 64 + f], acc);
            cur = b; acc = v;
        } else {
            acc += v;
        }
    }
    if (cur >= 0) atomicAdd(&g_pool[cur * 64 + f], acc);
}

// ---------------- head MLP ----------------
__global__ void k_head(const float* __restrict__ Wm1, const float* __restrict__ bm1,
                       const float* __restrict__ Wm2, const float* __restrict__ bm2,
                       float* __restrict__ outp) {
    __shared__ float sp[64];
    __shared__ float red[128];
    int b = blockIdx.x, j = threadIdx.x;
    if (j < 64) sp[j] = g_pool[b * 64 + j];
    __syncthreads();
    float v = 0.f;
    if (j < 100) {
        float a = bm1[j];
        #pragma unroll
        for (int k = 0; k < 64; k++) a += sp[k] * Wm1[k * 100 + j];
        v = fmaxf(a, 0.f) * Wm2[j];
    }
    red[j] = v;
    __syncthreads();
    for (int st = 64; st > 0; st >>= 1) {
        if (j < st) red[j] += red[j + st];
        __syncthreads();
    }
    if (j == 0) outp[b] = red[0] + bm2[0];
}

// ---------------- launch ----------------
extern "C" void kernel_launch(void* const* d_in, const int* in_sizes, int n_in,
                              void* d_out, int out_size) {
    const float* x    = (const float*)d_in[0];
    const float* ea   = (const float*)d_in[1];
    const int*   ei   = (const int*)  d_in[2];
    const int*   batch= (const int*)  d_in[3];
    const float* W1   = (const float*)d_in[4];
    const float* b1   = (const float*)d_in[5];
    const float* W2   = (const float*)d_in[6];
    const float* b2   = (const float*)d_in[7];
    const float* We   = (const float*)d_in[8];
    const float* be   = (const float*)d_in[9];
    const float* Wp   = (const float*)d_in[10];
    const float* bp   = (const float*)d_in[11];
    const float* Wo   = (const float*)d_in[12];
    const float* bo   = (const float*)d_in[13];
    const float* Wl   = (const float*)d_in[14];
    const float* bl   = (const float*)d_in[15];
    const float* gamma= (const float*)d_in[16];
    const float* beta = (const float*)d_in[17];
    const float* Wm1  = (const float*)d_in[18];
    const float* bm1  = (const float*)d_in[19];
    const float* Wm2  = (const float*)d_in[20];
    const float* bm2  = (const float*)d_in[21];

    int N = in_sizes[0] / FDIM;
    int E = in_sizes[1] / 16;

    static const double DEG[17] = {0,1000,2000,4000,8000,16000,24000,20000,12000,
                                   6000,3000,2000,1000,500,300,200,100};
    double snum = 0.0, sden = 0.0;
    for (int i = 0; i < 17; i++) { snum += log((double)i + 1.0) * DEG[i]; sden += DEG[i]; }
    float avg_log = (float)(snum / sden);

    int nb256 = (N + 255) / 256;
    int eb256 = (E + 255) / 256;

    k_init <<<nb256, 256>>>(N);                                           // 1
    k_wowl <<<(832 * FDIM + 255) / 256, 256>>>(Wo, Wl);                   // 2
    k_small<<<(7360 * 32 + 255) / 256, 256>>>(W2, b2, Wp, bp, We, be, bo, Wl, bl); // 3
    k_node <<<nb256, 256>>>(x, W1, b1, N);                                // 4
    k_count<<<eb256, 256>>>(ei, E);                                       // 5
    k_scan <<<(N + 1023) / 1024, 1024>>>(N);                              // 6
    k_fill <<<eb256, 256>>>(ei, E);                                       // 7
    k_agg  <<<(N + 7) / 8, 256>>>(ea, N, avg_log);                        // 8
    k_gemm <<<(N + GBM - 1) / GBM, 128>>>(N);                             // 9
    k_bn   <<<1, 64>>>(gamma, beta, N);                                   // 10
    k_pool <<<(N + 1023) / 1024, 256>>>(batch, N);                        // 11
    k_head <<<BGR, 128>>>(Wm1, bm1, Wm2, bm2, (float*)d_out);             // 12
}